// round 1
// baseline (speedup 1.0000x reference)
#include <cuda_runtime.h>
#include <math.h>

// ---------------------------------------------------------------------------
// GraphWaveNet forward, fp32.
// Layout convention: h, g, y tensors are [B, N, L, C] (channel innermost).
// ---------------------------------------------------------------------------

#define NLAYER 8
#define BATCH  16
#define NNODE  1024
#define L0     13
#define RC     32    // residual channels
#define DC     32    // dilation channels
#define SC     256   // skip channels
#define EC     512   // end channels
#define OCH    12    // out channels
#define EMBD   10
#define BN_EPS 1e-5f

// -------------------- device scratch (allocation-free) ---------------------
__device__ float g_adp  [NNODE * NNODE];                 // 4 MB
__device__ float g_h0   [BATCH * NNODE * L0 * RC];       // 27 MB
__device__ float g_h1   [BATCH * NNODE * L0 * RC];       // 27 MB
__device__ float g_y    [BATCH * NNODE * 12 * DC];       // 25 MB (max Lout=12)
__device__ float g_glast[BATCH * NNODE * DC];            // 2 MB
__device__ float g_skip [BATCH * NNODE * SC];            // 16 MB
__device__ float g_c1   [BATCH * NNODE * EC];            // 32 MB

// -------------------- adaptive adjacency: softmax(relu(E E^T)) -------------
__global__ void adp_kernel(const float* __restrict__ emb) {
    __shared__ float sE[EMBD];
    __shared__ float sm[NNODE];
    __shared__ float red[256];
    int v = blockIdx.x;
    int tid = threadIdx.x;
    if (tid < EMBD) sE[tid] = emb[v * EMBD + tid];
    __syncthreads();
    float lmax = -1e30f;
    for (int w = tid; w < NNODE; w += 256) {
        float dot = 0.f;
#pragma unroll
        for (int e = 0; e < EMBD; e++) dot += sE[e] * emb[w * EMBD + e];
        dot = fmaxf(dot, 0.f);
        sm[w] = dot;
        lmax = fmaxf(lmax, dot);
    }
    red[tid] = lmax; __syncthreads();
    for (int s = 128; s > 0; s >>= 1) {
        if (tid < s) red[tid] = fmaxf(red[tid], red[tid + s]);
        __syncthreads();
    }
    float mx = red[0]; __syncthreads();
    float lsum = 0.f;
    for (int w = tid; w < NNODE; w += 256) {
        float e = __expf(sm[w] - mx);
        sm[w] = e;
        lsum += e;
    }
    red[tid] = lsum; __syncthreads();
    for (int s = 128; s > 0; s >>= 1) {
        if (tid < s) red[tid] += red[tid + s];
        __syncthreads();
    }
    float inv = 1.0f / red[0];
    for (int w = tid; w < NNODE; w += 256)
        g_adp[v * NNODE + w] = sm[w] * inv;
}

// -------------------- start 1x1 conv (CIN=2 -> RC) --------------------------
__global__ void start_kernel(const float* __restrict__ x,
                             const float* __restrict__ w,
                             const float* __restrict__ b) {
    int idx = blockIdx.x * blockDim.x + threadIdx.x;
    if (idx >= BATCH * NNODE * L0 * RC) return;
    int c = idx & 31;
    int t = idx >> 5;
    int l = t % L0; t /= L0;
    int n = t % NNODE; t /= NNODE;
    int bb = t;
    const float* xp = x + (((size_t)bb * L0 + l) * NNODE + n) * 2;
    g_h0[idx] = w[c * 2 + 0] * xp[0] + w[c * 2 + 1] * xp[1] + b[c];
}

// -------------------- per-layer: tcn conv + gate + fused gcn 1x1 -----------
// One warp per (b,n,l) output position; lane = channel.
__global__ __launch_bounds__(256)
void tcn_kernel(int hin_sel,
                const float* __restrict__ tcn_w,   // [32,32,2] (layer slice)
                const float* __restrict__ tcn_b,   // [32]
                const float* __restrict__ gcn_w,   // [32,32]
                int L_in, int L_out, int dil) {
    __shared__ float w0s[32][32];   // [c][o]
    __shared__ float w1s[32][32];
    __shared__ float gws[32][32];
    __shared__ float sb[32];
    int tid = threadIdx.x;
    for (int i = tid; i < 1024; i += 256) {
        int o = i >> 5, c = i & 31;
        w0s[c][o] = tcn_w[(o * 32 + c) * 2 + 0];
        w1s[c][o] = tcn_w[(o * 32 + c) * 2 + 1];
        gws[c][o] = gcn_w[o * 32 + c];
    }
    if (tid < 32) sb[tid] = tcn_b[tid];
    __syncthreads();

    const float* h_in = hin_sel ? g_h1 : g_h0;
    int lane = tid & 31, warp = tid >> 5;
    int npos = BATCH * NNODE * L_out;
    int pos = blockIdx.x * 8 + warp;
    if (pos >= npos) return;

    int l  = pos % L_out;
    int bn = pos / L_out;
    const float* hp = h_in + ((size_t)bn * L_in + l) * 32;
    float h0 = hp[lane];
    float h1 = hp[dil * 32 + lane];
    float acc = sb[lane];
#pragma unroll
    for (int c = 0; c < 32; c++) {
        float v0 = __shfl_sync(0xffffffffu, h0, c);
        float v1 = __shfl_sync(0xffffffffu, h1, c);
        acc = fmaf(w0s[c][lane], v0, acc);
        acc = fmaf(w1s[c][lane], v1, acc);
    }
    float gate = tanhf(acc) * (1.0f / (1.0f + __expf(-acc)));
    float yv = 0.f;
#pragma unroll
    for (int c = 0; c < 32; c++) {
        float gv = __shfl_sync(0xffffffffu, gate, c);
        yv = fmaf(gws[c][lane], gv, yv);
    }
    g_y[(size_t)pos * 32 + lane] = yv;
    if (l == L_out - 1) g_glast[(size_t)bn * 32 + lane] = gate;
}

// -------------------- skip conv (only at last time step) -------------------
__global__ __launch_bounds__(256)
void skip_kernel(const float* __restrict__ skip_w,  // [256,32] layer slice
                 const float* __restrict__ skip_b,  // [256]
                 int first) {
    __shared__ float ws[32][SC];   // 32 KB
    int tid = threadIdx.x;
    for (int i = tid; i < 32 * SC; i += 256) {
        int s = i % SC, c = i / SC;
        ws[c][s] = skip_w[s * 32 + c];
    }
    __syncthreads();
    float bsv = skip_b[tid];
    for (int bn = blockIdx.x; bn < BATCH * NNODE; bn += gridDim.x) {
        const float* gp = g_glast + (size_t)bn * 32;
        float acc = bsv;
#pragma unroll
        for (int c = 0; c < 32; c++) acc = fmaf(ws[c][tid], __ldg(gp + c), acc);
        float* sp = g_skip + (size_t)bn * SC + tid;
        *sp = first ? acc : (*sp + acc);
    }
}

// -------------------- diffusion GEMM + epilogue -----------------------------
// C[w,j] = sum_v adp[v,w] * Y_b[v,j],  j = l*32 + r
// epilogue: relu(C + gcn_b[r]) + residual(h_in[b,w,l+dil,r]) then BN affine.
#define BM 128
#define BN 64
#define BK 16
__global__ __launch_bounds__(256)
void gcn_gemm_kernel(int hin_sel,
                     const float* __restrict__ gcn_b,
                     const float* __restrict__ bn_g,
                     const float* __restrict__ bn_be,
                     const float* __restrict__ bn_m,
                     const float* __restrict__ bn_v,
                     int L_in, int L_out, int dil) {
    __shared__ float As[BK][BM];
    __shared__ float Bs[BK][BN];
    const float* h_in  = hin_sel ? g_h1 : g_h0;
    float*       h_out = hin_sel ? g_h0 : g_h1;

    int ld = L_out * 32;
    int b  = blockIdx.z;
    int m0 = blockIdx.y * BM;     // node w
    int n0 = blockIdx.x * BN;     // j
    int tid = threadIdx.x;
    int tx = tid & 15, ty = tid >> 4;
    const float* Yb = g_y + (size_t)b * NNODE * ld;

    float acc[8][4];
#pragma unroll
    for (int i = 0; i < 8; i++)
#pragma unroll
        for (int j = 0; j < 4; j++) acc[i][j] = 0.f;

    for (int k0 = 0; k0 < NNODE; k0 += BK) {
#pragma unroll
        for (int i = 0; i < 8; i++) {
            int idx = tid + i * 256;
            int k = idx >> 7, m = idx & 127;
            As[k][m] = g_adp[(size_t)(k0 + k) * NNODE + m0 + m];
        }
#pragma unroll
        for (int i = 0; i < 4; i++) {
            int idx = tid + i * 256;
            int k = idx >> 6, n = idx & 63;
            int j = n0 + n;
            Bs[k][n] = (j < ld) ? Yb[(size_t)(k0 + k) * ld + j] : 0.f;
        }
        __syncthreads();
#pragma unroll
        for (int k = 0; k < BK; k++) {
            float a[8], bb[4];
#pragma unroll
            for (int i = 0; i < 8; i++) a[i] = As[k][ty * 8 + i];
#pragma unroll
            for (int j = 0; j < 4; j++) bb[j] = Bs[k][tx * 4 + j];
#pragma unroll
            for (int i = 0; i < 8; i++)
#pragma unroll
                for (int j = 0; j < 4; j++)
                    acc[i][j] = fmaf(a[i], bb[j], acc[i][j]);
        }
        __syncthreads();
    }

#pragma unroll
    for (int j = 0; j < 4; j++) {
        int jj = n0 + tx * 4 + j;
        if (jj >= ld) continue;
        int l = jj >> 5, r = jj & 31;
        float gb  = gcn_b[r];
        float inv = bn_g[r] * rsqrtf(bn_v[r] + BN_EPS);
        float mu  = bn_m[r], be = bn_be[r];
#pragma unroll
        for (int i = 0; i < 8; i++) {
            int w = m0 + ty * 8 + i;
            float val = fmaxf(acc[i][j] + gb, 0.f);
            val += h_in[(((size_t)b * NNODE + w) * L_in + l + dil) * 32 + r];
            val = (val - mu) * inv + be;
            h_out[(((size_t)b * NNODE + w) * L_out + l) * 32 + r] = val;
        }
    }
}

// -------------------- end1: relu(skip) -> 512, relu -------------------------
// C1[p,e] = relu( sum_s relu(skip[p,s]) * e1w[e,s] + e1b[e] )
__global__ __launch_bounds__(256)
void end1_kernel(const float* __restrict__ w, const float* __restrict__ bias) {
    __shared__ float As[BK][BM];
    __shared__ float Bs[BK][BN];
    int m0 = blockIdx.y * BM;   // p
    int n0 = blockIdx.x * BN;   // e
    int tid = threadIdx.x;
    int tx = tid & 15, ty = tid >> 4;

    float acc[8][4];
#pragma unroll
    for (int i = 0; i < 8; i++)
#pragma unroll
        for (int j = 0; j < 4; j++) acc[i][j] = 0.f;

    for (int k0 = 0; k0 < SC; k0 += BK) {
        {
            int m = tid & 127, kh = tid >> 7;      // kh in {0,1}
            const float* sp = g_skip + (size_t)(m0 + m) * SC + k0 + kh * 8;
#pragma unroll
            for (int j = 0; j < 8; j++) As[kh * 8 + j][m] = fmaxf(sp[j], 0.f);
        }
        {
            int n = tid & 63, kq = tid >> 6;       // kq in {0..3}
            const float* wp = w + (size_t)(n0 + n) * SC + k0 + kq * 4;
#pragma unroll
            for (int j = 0; j < 4; j++) Bs[kq * 4 + j][n] = wp[j];
        }
        __syncthreads();
#pragma unroll
        for (int k = 0; k < BK; k++) {
            float a[8], bb[4];
#pragma unroll
            for (int i = 0; i < 8; i++) a[i] = As[k][ty * 8 + i];
#pragma unroll
            for (int j = 0; j < 4; j++) bb[j] = Bs[k][tx * 4 + j];
#pragma unroll
            for (int i = 0; i < 8; i++)
#pragma unroll
                for (int j = 0; j < 4; j++)
                    acc[i][j] = fmaf(a[i], bb[j], acc[i][j]);
        }
        __syncthreads();
    }
#pragma unroll
    for (int j = 0; j < 4; j++) {
        int e = n0 + tx * 4 + j;
        float be = bias[e];
#pragma unroll
        for (int i = 0; i < 8; i++) {
            int p = m0 + ty * 8 + i;
            g_c1[(size_t)p * EC + e] = fmaxf(acc[i][j] + be, 0.f);
        }
    }
}

// -------------------- end2: 512 -> 12, write output -------------------------
__global__ __launch_bounds__(128)
void end2_kernel(const float* __restrict__ w, const float* __restrict__ bias,
                 float* __restrict__ out) {
    __shared__ float ws[OCH][EC];   // 24 KB
    int tid = threadIdx.x;
    for (int i = tid; i < OCH * EC; i += 128) ws[i / EC][i % EC] = w[i];
    __syncthreads();
    int p = blockIdx.x * 128 + tid;
    if (p >= BATCH * NNODE) return;
    const float* cp = g_c1 + (size_t)p * EC;
    float acc[OCH];
#pragma unroll
    for (int o = 0; o < OCH; o++) acc[o] = bias[o];
    for (int e = 0; e < EC; e += 4) {
        float4 v = *(const float4*)(cp + e);
#pragma unroll
        for (int o = 0; o < OCH; o++) {
            acc[o] = fmaf(ws[o][e + 0], v.x, acc[o]);
            acc[o] = fmaf(ws[o][e + 1], v.y, acc[o]);
            acc[o] = fmaf(ws[o][e + 2], v.z, acc[o]);
            acc[o] = fmaf(ws[o][e + 3], v.w, acc[o]);
        }
    }
#pragma unroll
    for (int o = 0; o < OCH; o++) out[(size_t)p * OCH + o] = acc[o];
}

// ---------------------------------------------------------------------------
extern "C" void kernel_launch(void* const* d_in, const int* in_sizes, int n_in,
                              void* d_out, int out_size) {
    const float* x       = (const float*)d_in[0];
    const float* emb     = (const float*)d_in[1];
    const float* start_w = (const float*)d_in[2];
    const float* start_b = (const float*)d_in[3];
    const float* tcn_w   = (const float*)d_in[4];
    const float* tcn_b   = (const float*)d_in[5];
    const float* skip_w  = (const float*)d_in[6];
    const float* skip_b  = (const float*)d_in[7];
    const float* gcn_w   = (const float*)d_in[8];
    const float* gcn_b   = (const float*)d_in[9];
    const float* bn_g    = (const float*)d_in[10];
    const float* bn_be   = (const float*)d_in[11];
    const float* bn_m    = (const float*)d_in[12];
    const float* bn_v    = (const float*)d_in[13];
    const float* e1w     = (const float*)d_in[14];
    const float* e1b     = (const float*)d_in[15];
    const float* e2w     = (const float*)d_in[16];
    const float* e2b     = (const float*)d_in[17];
    float* out = (float*)d_out;

    adp_kernel<<<NNODE, 256>>>(emb);
    start_kernel<<<(BATCH * NNODE * L0 * RC + 255) / 256, 256>>>(x, start_w, start_b);

    static const int DIL[NLAYER] = {1, 2, 1, 2, 1, 2, 1, 2};
    int L_in = L0;
    int hsel = 0;   // current h lives in g_h0 when hsel==0
    for (int i = 0; i < NLAYER; i++) {
        int d = DIL[i];
        int L_out = L_in - d;
        int npos = BATCH * NNODE * L_out;
        tcn_kernel<<<(npos + 7) / 8, 256>>>(
            hsel,
            tcn_w + (size_t)i * 32 * 32 * 2,
            tcn_b + (size_t)i * 32,
            gcn_w + (size_t)i * 32 * 32,
            L_in, L_out, d);
        skip_kernel<<<512, 256>>>(
            skip_w + (size_t)i * SC * 32,
            skip_b + (size_t)i * SC,
            i == 0 ? 1 : 0);
        int ld = L_out * 32;
        dim3 gridG((ld + BN - 1) / BN, NNODE / BM, BATCH);
        gcn_gemm_kernel<<<gridG, 256>>>(
            hsel,
            gcn_b + (size_t)i * 32,
            bn_g + (size_t)i * 32, bn_be + (size_t)i * 32,
            bn_m + (size_t)i * 32, bn_v + (size_t)i * 32,
            L_in, L_out, d);
        hsel ^= 1;   // gcn wrote the other buffer
        L_in = L_out;
    }

    dim3 gridE(EC / BN, (BATCH * NNODE) / BM);
    end1_kernel<<<gridE, 256>>>(e1w, e1b);
    end2_kernel<<<((BATCH * NNODE) + 127) / 128, 128>>>(e2w, e2b, out);
}

// round 3
// speedup vs baseline: 1.0504x; 1.0504x over previous
#include <cuda_runtime.h>
#include <math.h>

// ---------------------------------------------------------------------------
// GraphWaveNet forward, fp32.
// Layout convention: h, g, y tensors are [B, N, L, C] (channel innermost).
// ---------------------------------------------------------------------------

#define NLAYER 8
#define BATCH  16
#define NNODE  1024
#define L0     13
#define RC     32    // residual channels
#define DC     32    // dilation channels
#define SC     256   // skip channels
#define EC     512   // end channels
#define OCH    12    // out channels
#define EMBD   10
#define BN_EPS 1e-5f

// -------------------- device scratch (allocation-free) ---------------------
__device__ float g_adp  [NNODE * NNODE];                 // 4 MB
__device__ float g_h0   [BATCH * NNODE * L0 * RC];       // 27 MB
__device__ float g_h1   [BATCH * NNODE * L0 * RC];       // 27 MB
__device__ float g_y    [BATCH * NNODE * 12 * DC];       // 25 MB (max Lout=12)
__device__ float g_glast[BATCH * NNODE * DC];            // 2 MB
__device__ float g_skip [BATCH * NNODE * SC];            // 16 MB
__device__ float g_c1   [BATCH * NNODE * EC];            // 32 MB

// -------------------- adaptive adjacency: softmax(relu(E E^T)) -------------
__global__ void adp_kernel(const float* __restrict__ emb) {
    __shared__ float sE[EMBD];
    __shared__ float sm[NNODE];
    __shared__ float red[256];
    int v = blockIdx.x;
    int tid = threadIdx.x;
    if (tid < EMBD) sE[tid] = emb[v * EMBD + tid];
    __syncthreads();
    float lmax = -1e30f;
    for (int w = tid; w < NNODE; w += 256) {
        float dot = 0.f;
#pragma unroll
        for (int e = 0; e < EMBD; e++) dot += sE[e] * emb[w * EMBD + e];
        dot = fmaxf(dot, 0.f);
        sm[w] = dot;
        lmax = fmaxf(lmax, dot);
    }
    red[tid] = lmax; __syncthreads();
    for (int s = 128; s > 0; s >>= 1) {
        if (tid < s) red[tid] = fmaxf(red[tid], red[tid + s]);
        __syncthreads();
    }
    float mx = red[0]; __syncthreads();
    float lsum = 0.f;
    for (int w = tid; w < NNODE; w += 256) {
        float e = __expf(sm[w] - mx);
        sm[w] = e;
        lsum += e;
    }
    red[tid] = lsum; __syncthreads();
    for (int s = 128; s > 0; s >>= 1) {
        if (tid < s) red[tid] += red[tid + s];
        __syncthreads();
    }
    float inv = 1.0f / red[0];
    for (int w = tid; w < NNODE; w += 256)
        g_adp[v * NNODE + w] = sm[w] * inv;
}

// -------------------- start 1x1 conv (CIN=2 -> RC) --------------------------
__global__ void start_kernel(const float* __restrict__ x,
                             const float* __restrict__ w,
                             const float* __restrict__ b) {
    int idx = blockIdx.x * blockDim.x + threadIdx.x;
    if (idx >= BATCH * NNODE * L0 * RC) return;
    int c = idx & 31;
    int t = idx >> 5;
    int l = t % L0; t /= L0;
    int n = t % NNODE; t /= NNODE;
    int bb = t;
    const float* xp = x + (((size_t)bb * L0 + l) * NNODE + n) * 2;
    g_h0[idx] = w[c * 2 + 0] * xp[0] + w[c * 2 + 1] * xp[1] + b[c];
}

// -------------------- per-layer: tcn conv + gate + fused gcn 1x1 -----------
// One warp per (b,n,l) output position; lane = channel.
__global__ __launch_bounds__(256)
void tcn_kernel(int hin_sel,
                const float* __restrict__ tcn_w,   // [32,32,2] (layer slice)
                const float* __restrict__ tcn_b,   // [32]
                const float* __restrict__ gcn_w,   // [32,32]
                int L_in, int L_out, int dil) {
    __shared__ float w0s[32][32];   // [c][o]
    __shared__ float w1s[32][32];
    __shared__ float gws[32][32];
    __shared__ float sb[32];
    int tid = threadIdx.x;
    for (int i = tid; i < 1024; i += 256) {
        int o = i >> 5, c = i & 31;
        w0s[c][o] = tcn_w[(o * 32 + c) * 2 + 0];
        w1s[c][o] = tcn_w[(o * 32 + c) * 2 + 1];
        gws[c][o] = gcn_w[o * 32 + c];
    }
    if (tid < 32) sb[tid] = tcn_b[tid];
    __syncthreads();

    const float* h_in = hin_sel ? g_h1 : g_h0;
    int lane = tid & 31, warp = tid >> 5;
    int npos = BATCH * NNODE * L_out;
    int pos = blockIdx.x * 8 + warp;
    if (pos >= npos) return;

    int l  = pos % L_out;
    int bn = pos / L_out;
    const float* hp = h_in + ((size_t)bn * L_in + l) * 32;
    float h0 = hp[lane];
    float h1 = hp[dil * 32 + lane];
    float acc = sb[lane];
#pragma unroll
    for (int c = 0; c < 32; c++) {
        float v0 = __shfl_sync(0xffffffffu, h0, c);
        float v1 = __shfl_sync(0xffffffffu, h1, c);
        acc = fmaf(w0s[c][lane], v0, acc);
        acc = fmaf(w1s[c][lane], v1, acc);
    }
    float gate = tanhf(acc) * (1.0f / (1.0f + __expf(-acc)));
    float yv = 0.f;
#pragma unroll
    for (int c = 0; c < 32; c++) {
        float gv = __shfl_sync(0xffffffffu, gate, c);
        yv = fmaf(gws[c][lane], gv, yv);
    }
    g_y[(size_t)pos * 32 + lane] = yv;
    if (l == L_out - 1) g_glast[(size_t)bn * 32 + lane] = gate;
}

// -------------------- skip conv (only at last time step) -------------------
__global__ __launch_bounds__(256)
void skip_kernel(const float* __restrict__ skip_w,  // [256,32] layer slice
                 const float* __restrict__ skip_b,  // [256]
                 int first) {
    __shared__ float ws[32][SC];   // 32 KB
    int tid = threadIdx.x;
    for (int i = tid; i < 32 * SC; i += 256) {
        int s = i % SC, c = i / SC;
        ws[c][s] = skip_w[s * 32 + c];
    }
    __syncthreads();
    float bsv = skip_b[tid];
    for (int bn = blockIdx.x; bn < BATCH * NNODE; bn += gridDim.x) {
        const float* gp = g_glast + (size_t)bn * 32;
        float acc = bsv;
#pragma unroll
        for (int c = 0; c < 32; c++) acc = fmaf(ws[c][tid], __ldg(gp + c), acc);
        float* sp = g_skip + (size_t)bn * SC + tid;
        *sp = first ? acc : (*sp + acc);
    }
}

// -------------------- diffusion GEMM + epilogue -----------------------------
// C[w,j] = sum_v adp[v,w] * Y_b[v,j],  j = l*32 + r
// epilogue: relu(C + gcn_b[r]) + residual(h_in[b,w,l+dil,r]) then BN affine.
#define BM 128
#define BN 64
#define BK 16
__global__ __launch_bounds__(256)
void gcn_gemm_kernel(int hin_sel,
                     const float* __restrict__ gcn_b,
                     const float* __restrict__ bn_g,
                     const float* __restrict__ bn_be,
                     const float* __restrict__ bn_m,
                     const float* __restrict__ bn_v,
                     int L_in, int L_out, int dil) {
    __shared__ float As[BK][BM];
    __shared__ float Bs[BK][BN];
    const float* h_in  = hin_sel ? g_h1 : g_h0;
    float*       h_out = hin_sel ? g_h0 : g_h1;

    int ld = L_out * 32;
    int b  = blockIdx.z;
    int m0 = blockIdx.y * BM;     // node w
    int n0 = blockIdx.x * BN;     // j
    int tid = threadIdx.x;
    int tx = tid & 15, ty = tid >> 4;
    const float* Yb = g_y + (size_t)b * NNODE * ld;

    float acc[8][4];
#pragma unroll
    for (int i = 0; i < 8; i++)
#pragma unroll
        for (int j = 0; j < 4; j++) acc[i][j] = 0.f;

    for (int k0 = 0; k0 < NNODE; k0 += BK) {
#pragma unroll
        for (int i = 0; i < 8; i++) {
            int idx = tid + i * 256;
            int k = idx >> 7, m = idx & 127;
            As[k][m] = g_adp[(size_t)(k0 + k) * NNODE + m0 + m];
        }
#pragma unroll
        for (int i = 0; i < 4; i++) {
            int idx = tid + i * 256;
            int k = idx >> 6, n = idx & 63;
            int j = n0 + n;
            Bs[k][n] = (j < ld) ? Yb[(size_t)(k0 + k) * ld + j] : 0.f;
        }
        __syncthreads();
#pragma unroll
        for (int k = 0; k < BK; k++) {
            float a[8], bb[4];
#pragma unroll
            for (int i = 0; i < 8; i++) a[i] = As[k][ty * 8 + i];
#pragma unroll
            for (int j = 0; j < 4; j++) bb[j] = Bs[k][tx * 4 + j];
#pragma unroll
            for (int i = 0; i < 8; i++)
#pragma unroll
                for (int j = 0; j < 4; j++)
                    acc[i][j] = fmaf(a[i], bb[j], acc[i][j]);
        }
        __syncthreads();
    }

#pragma unroll
    for (int j = 0; j < 4; j++) {
        int jj = n0 + tx * 4 + j;
        if (jj >= ld) continue;
        int l = jj >> 5, r = jj & 31;
        float gb  = gcn_b[r];
        float inv = bn_g[r] * rsqrtf(bn_v[r] + BN_EPS);
        float mu  = bn_m[r], be = bn_be[r];
#pragma unroll
        for (int i = 0; i < 8; i++) {
            int w = m0 + ty * 8 + i;
            float val = fmaxf(acc[i][j] + gb, 0.f);
            val += h_in[(((size_t)b * NNODE + w) * L_in + l + dil) * 32 + r];
            val = (val - mu) * inv + be;
            h_out[(((size_t)b * NNODE + w) * L_out + l) * 32 + r] = val;
        }
    }
}

// -------------------- end1: relu(skip) -> 512, relu -------------------------
// C1[p,e] = relu( sum_s relu(skip[p,s]) * e1w[e,s] + e1b[e] )
__global__ __launch_bounds__(256)
void end1_kernel(const float* __restrict__ w, const float* __restrict__ bias) {
    __shared__ float As[BK][BM];
    __shared__ float Bs[BK][BN];
    int m0 = blockIdx.y * BM;   // p
    int n0 = blockIdx.x * BN;   // e
    int tid = threadIdx.x;
    int tx = tid & 15, ty = tid >> 4;

    float acc[8][4];
#pragma unroll
    for (int i = 0; i < 8; i++)
#pragma unroll
        for (int j = 0; j < 4; j++) acc[i][j] = 0.f;

    for (int k0 = 0; k0 < SC; k0 += BK) {
        {
            int m = tid & 127, kh = tid >> 7;      // kh in {0,1}
            const float* sp = g_skip + (size_t)(m0 + m) * SC + k0 + kh * 8;
#pragma unroll
            for (int j = 0; j < 8; j++) As[kh * 8 + j][m] = fmaxf(sp[j], 0.f);
        }
        {
            int n = tid & 63, kq = tid >> 6;       // kq in {0..3}
            const float* wp = w + (size_t)(n0 + n) * SC + k0 + kq * 4;
#pragma unroll
            for (int j = 0; j < 4; j++) Bs[kq * 4 + j][n] = wp[j];
        }
        __syncthreads();
#pragma unroll
        for (int k = 0; k < BK; k++) {
            float a[8], bb[4];
#pragma unroll
            for (int i = 0; i < 8; i++) a[i] = As[k][ty * 8 + i];
#pragma unroll
            for (int j = 0; j < 4; j++) bb[j] = Bs[k][tx * 4 + j];
#pragma unroll
            for (int i = 0; i < 8; i++)
#pragma unroll
                for (int j = 0; j < 4; j++)
                    acc[i][j] = fmaf(a[i], bb[j], acc[i][j]);
        }
        __syncthreads();
    }
#pragma unroll
    for (int j = 0; j < 4; j++) {
        int e = n0 + tx * 4 + j;
        float be = bias[e];
#pragma unroll
        for (int i = 0; i < 8; i++) {
            int p = m0 + ty * 8 + i;
            g_c1[(size_t)p * EC + e] = fmaxf(acc[i][j] + be, 0.f);
        }
    }
}

// -------------------- end2: 512 -> 12, write output -------------------------
__global__ __launch_bounds__(128)
void end2_kernel(const float* __restrict__ w, const float* __restrict__ bias,
                 float* __restrict__ out) {
    __shared__ float ws[OCH][EC];   // 24 KB
    int tid = threadIdx.x;
    for (int i = tid; i < OCH * EC; i += 128) ws[i / EC][i % EC] = w[i];
    __syncthreads();
    int p = blockIdx.x * 128 + tid;
    if (p >= BATCH * NNODE) return;
    const float* cp = g_c1 + (size_t)p * EC;
    float acc[OCH];
#pragma unroll
    for (int o = 0; o < OCH; o++) acc[o] = bias[o];
    for (int e = 0; e < EC; e += 4) {
        float4 v = *(const float4*)(cp + e);
#pragma unroll
        for (int o = 0; o < OCH; o++) {
            acc[o] = fmaf(ws[o][e + 0], v.x, acc[o]);
            acc[o] = fmaf(ws[o][e + 1], v.y, acc[o]);
            acc[o] = fmaf(ws[o][e + 2], v.z, acc[o]);
            acc[o] = fmaf(ws[o][e + 3], v.w, acc[o]);
        }
    }
#pragma unroll
    for (int o = 0; o < OCH; o++) out[(size_t)p * OCH + o] = acc[o];
}

// ---------------------------------------------------------------------------
extern "C" void kernel_launch(void* const* d_in, const int* in_sizes, int n_in,
                              void* d_out, int out_size) {
    const float* x       = (const float*)d_in[0];
    const float* emb     = (const float*)d_in[1];
    const float* start_w = (const float*)d_in[2];
    const float* start_b = (const float*)d_in[3];
    const float* tcn_w   = (const float*)d_in[4];
    const float* tcn_b   = (const float*)d_in[5];
    const float* skip_w  = (const float*)d_in[6];
    const float* skip_b  = (const float*)d_in[7];
    const float* gcn_w   = (const float*)d_in[8];
    const float* gcn_b   = (const float*)d_in[9];
    const float* bn_g    = (const float*)d_in[10];
    const float* bn_be   = (const float*)d_in[11];
    const float* bn_m    = (const float*)d_in[12];
    const float* bn_v    = (const float*)d_in[13];
    const float* e1w     = (const float*)d_in[14];
    const float* e1b     = (const float*)d_in[15];
    const float* e2w     = (const float*)d_in[16];
    const float* e2b     = (const float*)d_in[17];
    float* out = (float*)d_out;

    adp_kernel<<<NNODE, 256>>>(emb);
    start_kernel<<<(BATCH * NNODE * L0 * RC + 255) / 256, 256>>>(x, start_w, start_b);

    static const int DIL[NLAYER] = {1, 2, 1, 2, 1, 2, 1, 2};
    int L_in = L0;
    int hsel = 0;   // current h lives in g_h0 when hsel==0
    for (int i = 0; i < NLAYER; i++) {
        int d = DIL[i];
        int L_out = L_in - d;
        int npos = BATCH * NNODE * L_out;
        tcn_kernel<<<(npos + 7) / 8, 256>>>(
            hsel,
            tcn_w + (size_t)i * 32 * 32 * 2,
            tcn_b + (size_t)i * 32,
            gcn_w + (size_t)i * 32 * 32,
            L_in, L_out, d);
        skip_kernel<<<512, 256>>>(
            skip_w + (size_t)i * SC * 32,
            skip_b + (size_t)i * SC,
            i == 0 ? 1 : 0);
        int ld = L_out * 32;
        dim3 gridG((ld + BN - 1) / BN, NNODE / BM, BATCH);
        gcn_gemm_kernel<<<gridG, 256>>>(
            hsel,
            gcn_b + (size_t)i * 32,
            bn_g + (size_t)i * 32, bn_be + (size_t)i * 32,
            bn_m + (size_t)i * 32, bn_v + (size_t)i * 32,
            L_in, L_out, d);
        hsel ^= 1;   // gcn wrote the other buffer
        L_in = L_out;
    }

    dim3 gridE(EC / BN, (BATCH * NNODE) / BM);
    end1_kernel<<<gridE, 256>>>(e1w, e1b);
    end2_kernel<<<((BATCH * NNODE) + 127) / 128, 128>>>(e2w, e2b, out);
}

// round 9
// speedup vs baseline: 1.1767x; 1.1202x over previous
#include <cuda_runtime.h>
#include <math.h>

// ---------------------------------------------------------------------------
// GraphWaveNet forward, fp32. Base: Round-3 passing kernel.
// Layout convention: h, g, y tensors are [B, N, L, C] (channel innermost),
// row index bn = b*NNODE + n.
// Deltas vs R3: batched skip path (glast[bn][256] + one GEMM), last-layer
// gcn eliminated.
// ---------------------------------------------------------------------------

#define NLAYER 8
#define BATCH  16
#define NNODE  1024
#define L0     13
#define RC     32    // residual channels
#define DC     32    // dilation channels
#define SC     256   // skip channels
#define EC     512   // end channels
#define OCH    12    // out channels
#define EMBD   10
#define BN_EPS 1e-5f

// -------------------- device scratch (allocation-free) ---------------------
__device__ float g_adp  [NNODE * NNODE];                 // 4 MB
__device__ float g_h0   [BATCH * NNODE * L0 * RC];       // 27 MB
__device__ float g_h1   [BATCH * NNODE * L0 * RC];       // 27 MB
__device__ float g_y    [BATCH * NNODE * 12 * DC];       // 25 MB (max Lout=12)
__device__ float g_glast[BATCH * NNODE * 256];           // 16 MB [bn][layer*32+c]
__device__ float g_skip [BATCH * NNODE * SC];            // 16 MB
__device__ float g_c1   [BATCH * NNODE * EC];            // 32 MB
__device__ float g_W2   [256 * 256];                     // [s][k] combined skip w
__device__ float g_sb2  [256];                           // summed skip bias

// -------------------- adaptive adjacency: softmax(relu(E E^T)) -------------
__global__ void adp_kernel(const float* __restrict__ emb) {
    __shared__ float sE[EMBD];
    __shared__ float sm[NNODE];
    __shared__ float red[256];
    int v = blockIdx.x;
    int tid = threadIdx.x;
    if (tid < EMBD) sE[tid] = emb[v * EMBD + tid];
    __syncthreads();
    float lmax = -1e30f;
    for (int w = tid; w < NNODE; w += 256) {
        float dot = 0.f;
#pragma unroll
        for (int e = 0; e < EMBD; e++) dot += sE[e] * emb[w * EMBD + e];
        dot = fmaxf(dot, 0.f);
        sm[w] = dot;
        lmax = fmaxf(lmax, dot);
    }
    red[tid] = lmax; __syncthreads();
    for (int s = 128; s > 0; s >>= 1) {
        if (tid < s) red[tid] = fmaxf(red[tid], red[tid + s]);
        __syncthreads();
    }
    float mx = red[0]; __syncthreads();
    float lsum = 0.f;
    for (int w = tid; w < NNODE; w += 256) {
        float e = __expf(sm[w] - mx);
        sm[w] = e;
        lsum += e;
    }
    red[tid] = lsum; __syncthreads();
    for (int s = 128; s > 0; s >>= 1) {
        if (tid < s) red[tid] += red[tid + s];
        __syncthreads();
    }
    float inv = 1.0f / red[0];
    for (int w = tid; w < NNODE; w += 256)
        g_adp[v * NNODE + w] = sm[w] * inv;
}

// -------------------- start 1x1 conv (CIN=2 -> RC) --------------------------
__global__ void start_kernel(const float* __restrict__ x,
                             const float* __restrict__ w,
                             const float* __restrict__ b) {
    int idx = blockIdx.x * blockDim.x + threadIdx.x;
    if (idx >= BATCH * NNODE * L0 * RC) return;
    int c = idx & 31;
    int t = idx >> 5;
    int l = t % L0; t /= L0;
    int n = t % NNODE; t /= NNODE;
    int bb = t;
    const float* xp = x + (((size_t)bb * L0 + l) * NNODE + n) * 2;
    g_h0[idx] = w[c * 2 + 0] * xp[0] + w[c * 2 + 1] * xp[1] + b[c];
}

// -------------------- per-layer: tcn conv + gate + fused gcn 1x1 -----------
// One warp per (b,n,l) output position; lane = channel.
__global__ __launch_bounds__(256)
void tcn_kernel(int hin_sel,
                const float* __restrict__ tcn_w,   // [32,32,2] (layer slice)
                const float* __restrict__ tcn_b,   // [32]
                const float* __restrict__ gcn_w,   // [32,32]
                int L_in, int L_out, int dil, int layer, int write_y) {
    __shared__ float w0s[32][32];   // [c][o]
    __shared__ float w1s[32][32];
    __shared__ float gws[32][32];
    __shared__ float sb[32];
    int tid = threadIdx.x;
    for (int i = tid; i < 1024; i += 256) {
        int o = i >> 5, c = i & 31;
        w0s[c][o] = tcn_w[(o * 32 + c) * 2 + 0];
        w1s[c][o] = tcn_w[(o * 32 + c) * 2 + 1];
        gws[c][o] = gcn_w[o * 32 + c];
    }
    if (tid < 32) sb[tid] = tcn_b[tid];
    __syncthreads();

    const float* h_in = hin_sel ? g_h1 : g_h0;
    int lane = tid & 31, warp = tid >> 5;
    int npos = BATCH * NNODE * L_out;
    int pos = blockIdx.x * 8 + warp;
    if (pos >= npos) return;

    int l  = pos % L_out;
    int bn = pos / L_out;
    const float* hp = h_in + ((size_t)bn * L_in + l) * 32;
    float h0 = hp[lane];
    float h1 = hp[dil * 32 + lane];
    float acc = sb[lane];
#pragma unroll
    for (int c = 0; c < 32; c++) {
        float v0 = __shfl_sync(0xffffffffu, h0, c);
        float v1 = __shfl_sync(0xffffffffu, h1, c);
        acc = fmaf(w0s[c][lane], v0, acc);
        acc = fmaf(w1s[c][lane], v1, acc);
    }
    float gate = tanhf(acc) * (1.0f / (1.0f + __expf(-acc)));
    if (write_y) {
        float yv = 0.f;
#pragma unroll
        for (int c = 0; c < 32; c++) {
            float gv = __shfl_sync(0xffffffffu, gate, c);
            yv = fmaf(gws[c][lane], gv, yv);
        }
        g_y[(size_t)pos * 32 + lane] = yv;
    }
    if (l == L_out - 1)
        g_glast[(size_t)bn * 256 + layer * 32 + lane] = gate;
}

// -------------------- diffusion GEMM + epilogue -----------------------------
// C[w,j] = sum_v adp[v,w] * Y_b[v,j],  j = l*32 + r
// epilogue: relu(C + gcn_b[r]) + residual(h_in[b,w,l+dil,r]) then BN affine.
#define BM 128
#define BN 64
#define BK 16
__global__ __launch_bounds__(256)
void gcn_gemm_kernel(int hin_sel,
                     const float* __restrict__ gcn_b,
                     const float* __restrict__ bn_g,
                     const float* __restrict__ bn_be,
                     const float* __restrict__ bn_m,
                     const float* __restrict__ bn_v,
                     int L_in, int L_out, int dil) {
    __shared__ float As[BK][BM];
    __shared__ float Bs[BK][BN];
    const float* h_in  = hin_sel ? g_h1 : g_h0;
    float*       h_out = hin_sel ? g_h0 : g_h1;

    int ld = L_out * 32;
    int b  = blockIdx.z;
    int m0 = blockIdx.y * BM;     // node w
    int n0 = blockIdx.x * BN;     // j
    int tid = threadIdx.x;
    int tx = tid & 15, ty = tid >> 4;
    const float* Yb = g_y + (size_t)b * NNODE * ld;

    float acc[8][4];
#pragma unroll
    for (int i = 0; i < 8; i++)
#pragma unroll
        for (int j = 0; j < 4; j++) acc[i][j] = 0.f;

    for (int k0 = 0; k0 < NNODE; k0 += BK) {
#pragma unroll
        for (int i = 0; i < 8; i++) {
            int idx = tid + i * 256;
            int k = idx >> 7, m = idx & 127;
            As[k][m] = g_adp[(size_t)(k0 + k) * NNODE + m0 + m];
        }
#pragma unroll
        for (int i = 0; i < 4; i++) {
            int idx = tid + i * 256;
            int k = idx >> 6, n = idx & 63;
            int j = n0 + n;
            Bs[k][n] = (j < ld) ? Yb[(size_t)(k0 + k) * ld + j] : 0.f;
        }
        __syncthreads();
#pragma unroll
        for (int k = 0; k < BK; k++) {
            float a[8], bb[4];
#pragma unroll
            for (int i = 0; i < 8; i++) a[i] = As[k][ty * 8 + i];
#pragma unroll
            for (int j = 0; j < 4; j++) bb[j] = Bs[k][tx * 4 + j];
#pragma unroll
            for (int i = 0; i < 8; i++)
#pragma unroll
                for (int j = 0; j < 4; j++)
                    acc[i][j] = fmaf(a[i], bb[j], acc[i][j]);
        }
        __syncthreads();
    }

#pragma unroll
    for (int j = 0; j < 4; j++) {
        int jj = n0 + tx * 4 + j;
        if (jj >= ld) continue;
        int l = jj >> 5, r = jj & 31;
        float gb  = gcn_b[r];
        float inv = bn_g[r] * rsqrtf(bn_v[r] + BN_EPS);
        float mu  = bn_m[r], be = bn_be[r];
#pragma unroll
        for (int i = 0; i < 8; i++) {
            int w = m0 + ty * 8 + i;
            float val = fmaxf(acc[i][j] + gb, 0.f);
            val += h_in[(((size_t)b * NNODE + w) * L_in + l + dil) * 32 + r];
            val = (val - mu) * inv + be;
            h_out[(((size_t)b * NNODE + w) * L_out + l) * 32 + r] = val;
        }
    }
}

// -------------------- prep: combined skip weights [s][k] + summed bias -----
__global__ void prep_kernel(const float* __restrict__ skip_w,
                            const float* __restrict__ skip_b) {
    int idx = blockIdx.x * blockDim.x + threadIdx.x;
    if (idx < 256 * 256) {
        int s = idx >> 8, k = idx & 255;
        // skip_w[NLAYER][SC][32]: layer = k>>5, channel = k&31
        g_W2[idx] = skip_w[(size_t)(k >> 5) * (SC * 32) + s * 32 + (k & 31)];
    } else if (idx < 256 * 256 + 256) {
        int s = idx - 256 * 256;
        float acc = 0.f;
#pragma unroll
        for (int i = 0; i < 8; i++) acc += skip_b[i * 256 + s];
        g_sb2[s] = acc;
    }
}

// -------------------- batched skip GEMM -------------------------------------
// skip[p][s] = sum_k glast[p][k] * W2[s][k] + sb2[s]
__global__ __launch_bounds__(256)
void skip_gemm_kernel() {
    __shared__ float As[BK][BM];
    __shared__ float Bs[BK][BN];
    int m0 = blockIdx.y * BM;   // p
    int n0 = blockIdx.x * BN;   // s
    int tid = threadIdx.x;
    int tx = tid & 15, ty = tid >> 4;

    float acc[8][4];
#pragma unroll
    for (int i = 0; i < 8; i++)
#pragma unroll
        for (int j = 0; j < 4; j++) acc[i][j] = 0.f;

    for (int k0 = 0; k0 < 256; k0 += BK) {
        {
            int m = tid & 127, kh = tid >> 7;      // kh in {0,1}
            const float* gp = g_glast + (size_t)(m0 + m) * 256 + k0 + kh * 8;
#pragma unroll
            for (int j = 0; j < 8; j++) As[kh * 8 + j][m] = gp[j];
        }
        {
            int n = tid & 63, kq = tid >> 6;       // kq in {0..3}
            const float* wp = g_W2 + (size_t)(n0 + n) * 256 + k0 + kq * 4;
#pragma unroll
            for (int j = 0; j < 4; j++) Bs[kq * 4 + j][n] = wp[j];
        }
        __syncthreads();
#pragma unroll
        for (int k = 0; k < BK; k++) {
            float a[8], bb[4];
#pragma unroll
            for (int i = 0; i < 8; i++) a[i] = As[k][ty * 8 + i];
#pragma unroll
            for (int j = 0; j < 4; j++) bb[j] = Bs[k][tx * 4 + j];
#pragma unroll
            for (int i = 0; i < 8; i++)
#pragma unroll
                for (int j = 0; j < 4; j++)
                    acc[i][j] = fmaf(a[i], bb[j], acc[i][j]);
        }
        __syncthreads();
    }
#pragma unroll
    for (int j = 0; j < 4; j++) {
        int s = n0 + tx * 4 + j;
        float be = g_sb2[s];
#pragma unroll
        for (int i = 0; i < 8; i++) {
            int p = m0 + ty * 8 + i;
            g_skip[(size_t)p * SC + s] = acc[i][j] + be;
        }
    }
}

// -------------------- end1: relu(skip) -> 512, relu -------------------------
__global__ __launch_bounds__(256)
void end1_kernel(const float* __restrict__ w, const float* __restrict__ bias) {
    __shared__ float As[BK][BM];
    __shared__ float Bs[BK][BN];
    int m0 = blockIdx.y * BM;   // p
    int n0 = blockIdx.x * BN;   // e
    int tid = threadIdx.x;
    int tx = tid & 15, ty = tid >> 4;

    float acc[8][4];
#pragma unroll
    for (int i = 0; i < 8; i++)
#pragma unroll
        for (int j = 0; j < 4; j++) acc[i][j] = 0.f;

    for (int k0 = 0; k0 < SC; k0 += BK) {
        {
            int m = tid & 127, kh = tid >> 7;
            const float* sp = g_skip + (size_t)(m0 + m) * SC + k0 + kh * 8;
#pragma unroll
            for (int j = 0; j < 8; j++) As[kh * 8 + j][m] = fmaxf(sp[j], 0.f);
        }
        {
            int n = tid & 63, kq = tid >> 6;
            const float* wp = w + (size_t)(n0 + n) * SC + k0 + kq * 4;
#pragma unroll
            for (int j = 0; j < 4; j++) Bs[kq * 4 + j][n] = wp[j];
        }
        __syncthreads();
#pragma unroll
        for (int k = 0; k < BK; k++) {
            float a[8], bb[4];
#pragma unroll
            for (int i = 0; i < 8; i++) a[i] = As[k][ty * 8 + i];
#pragma unroll
            for (int j = 0; j < 4; j++) bb[j] = Bs[k][tx * 4 + j];
#pragma unroll
            for (int i = 0; i < 8; i++)
#pragma unroll
                for (int j = 0; j < 4; j++)
                    acc[i][j] = fmaf(a[i], bb[j], acc[i][j]);
        }
        __syncthreads();
    }
#pragma unroll
    for (int j = 0; j < 4; j++) {
        int e = n0 + tx * 4 + j;
        float be = bias[e];
#pragma unroll
        for (int i = 0; i < 8; i++) {
            int p = m0 + ty * 8 + i;
            g_c1[(size_t)p * EC + e] = fmaxf(acc[i][j] + be, 0.f);
        }
    }
}

// -------------------- end2: 512 -> 12, write output -------------------------
__global__ __launch_bounds__(128)
void end2_kernel(const float* __restrict__ w, const float* __restrict__ bias,
                 float* __restrict__ out) {
    __shared__ float ws[OCH][EC];   // 24 KB
    int tid = threadIdx.x;
    for (int i = tid; i < OCH * EC; i += 128) ws[i / EC][i % EC] = w[i];
    __syncthreads();
    int p = blockIdx.x * 128 + tid;
    if (p >= BATCH * NNODE) return;
    const float* cp = g_c1 + (size_t)p * EC;
    float acc[OCH];
#pragma unroll
    for (int o = 0; o < OCH; o++) acc[o] = bias[o];
    for (int e = 0; e < EC; e += 4) {
        float4 v = *(const float4*)(cp + e);
#pragma unroll
        for (int o = 0; o < OCH; o++) {
            acc[o] = fmaf(ws[o][e + 0], v.x, acc[o]);
            acc[o] = fmaf(ws[o][e + 1], v.y, acc[o]);
            acc[o] = fmaf(ws[o][e + 2], v.z, acc[o]);
            acc[o] = fmaf(ws[o][e + 3], v.w, acc[o]);
        }
    }
#pragma unroll
    for (int o = 0; o < OCH; o++) out[(size_t)p * OCH + o] = acc[o];
}

// ---------------------------------------------------------------------------
extern "C" void kernel_launch(void* const* d_in, const int* in_sizes, int n_in,
                              void* d_out, int out_size) {
    const float* x       = (const float*)d_in[0];
    const float* emb     = (const float*)d_in[1];
    const float* start_w = (const float*)d_in[2];
    const float* start_b = (const float*)d_in[3];
    const float* tcn_w   = (const float*)d_in[4];
    const float* tcn_b   = (const float*)d_in[5];
    const float* skip_w  = (const float*)d_in[6];
    const float* skip_b  = (const float*)d_in[7];
    const float* gcn_w   = (const float*)d_in[8];
    const float* gcn_b   = (const float*)d_in[9];
    const float* bn_g    = (const float*)d_in[10];
    const float* bn_be   = (const float*)d_in[11];
    const float* bn_m    = (const float*)d_in[12];
    const float* bn_v    = (const float*)d_in[13];
    const float* e1w     = (const float*)d_in[14];
    const float* e1b     = (const float*)d_in[15];
    const float* e2w     = (const float*)d_in[16];
    const float* e2b     = (const float*)d_in[17];
    float* out = (float*)d_out;

    adp_kernel<<<NNODE, 256>>>(emb);
    start_kernel<<<(BATCH * NNODE * L0 * RC + 255) / 256, 256>>>(x, start_w, start_b);
    prep_kernel<<<(256 * 256 + 256 + 255) / 256, 256>>>(skip_w, skip_b);

    static const int DIL[NLAYER] = {1, 2, 1, 2, 1, 2, 1, 2};
    int L_in = L0;
    int hsel = 0;   // current h lives in g_h0 when hsel==0
    for (int i = 0; i < NLAYER; i++) {
        int d = DIL[i];
        int L_out = L_in - d;
        int last = (i == NLAYER - 1);
        int npos = BATCH * NNODE * L_out;
        tcn_kernel<<<(npos + 7) / 8, 256>>>(
            hsel,
            tcn_w + (size_t)i * 32 * 32 * 2,
            tcn_b + (size_t)i * 32,
            gcn_w + (size_t)i * 32 * 32,
            L_in, L_out, d, i, last ? 0 : 1);
        if (!last) {
            int ld = L_out * 32;
            dim3 gridG((ld + BN - 1) / BN, NNODE / BM, BATCH);
            gcn_gemm_kernel<<<gridG, 256>>>(
                hsel,
                gcn_b + (size_t)i * 32,
                bn_g + (size_t)i * 32, bn_be + (size_t)i * 32,
                bn_m + (size_t)i * 32, bn_v + (size_t)i * 32,
                L_in, L_out, d);
            hsel ^= 1;   // gcn wrote the other buffer
        }
        L_in = L_out;
    }

    // batched skip: [16384 x 256] @ W2[s][k]^T + summed bias
    skip_gemm_kernel<<<dim3(SC / BN, (BATCH * NNODE) / BM), 256>>>();
    dim3 gridE(EC / BN, (BATCH * NNODE) / BM);
    end1_kernel<<<gridE, 256>>>(e1w, e1b);
    end2_kernel<<<((BATCH * NNODE) + 127) / 128, 128>>>(e2w, e2b, out);
}

// round 12
// speedup vs baseline: 1.7231x; 1.4644x over previous
#include <cuda_runtime.h>
#include <math.h>

// ---------------------------------------------------------------------------
// GraphWaveNet forward, fp32. Base: Round-9 passing kernel (4050us).
// Delta: tcn restructured one-warp-per-(b,n) with templated full unroll.
// Layout: h, y are [B, N, L, C] channel-innermost, row index bn = b*NNODE+n.
// ---------------------------------------------------------------------------

#define NLAYER 8
#define BATCH  16
#define NNODE  1024
#define L0     13
#define RC     32
#define DC     32
#define SC     256
#define EC     512
#define OCH    12
#define EMBD   10
#define BN_EPS 1e-5f

// -------------------- device scratch (allocation-free) ---------------------
__device__ float g_adp  [NNODE * NNODE];
__device__ float g_h0   [BATCH * NNODE * L0 * RC];
__device__ float g_h1   [BATCH * NNODE * L0 * RC];
__device__ float g_y    [BATCH * NNODE * 12 * DC];
__device__ float g_glast[BATCH * NNODE * 256];
__device__ float g_skip [BATCH * NNODE * SC];
__device__ float g_c1   [BATCH * NNODE * EC];
__device__ float g_W2   [256 * 256];
__device__ float g_sb2  [256];

// -------------------- adaptive adjacency: softmax(relu(E E^T)) -------------
__global__ void adp_kernel(const float* __restrict__ emb) {
    __shared__ float sE[EMBD];
    __shared__ float sm[NNODE];
    __shared__ float red[256];
    int v = blockIdx.x;
    int tid = threadIdx.x;
    if (tid < EMBD) sE[tid] = emb[v * EMBD + tid];
    __syncthreads();
    float lmax = -1e30f;
    for (int w = tid; w < NNODE; w += 256) {
        float dot = 0.f;
#pragma unroll
        for (int e = 0; e < EMBD; e++) dot += sE[e] * emb[w * EMBD + e];
        dot = fmaxf(dot, 0.f);
        sm[w] = dot;
        lmax = fmaxf(lmax, dot);
    }
    red[tid] = lmax; __syncthreads();
    for (int s = 128; s > 0; s >>= 1) {
        if (tid < s) red[tid] = fmaxf(red[tid], red[tid + s]);
        __syncthreads();
    }
    float mx = red[0]; __syncthreads();
    float lsum = 0.f;
    for (int w = tid; w < NNODE; w += 256) {
        float e = __expf(sm[w] - mx);
        sm[w] = e;
        lsum += e;
    }
    red[tid] = lsum; __syncthreads();
    for (int s = 128; s > 0; s >>= 1) {
        if (tid < s) red[tid] += red[tid + s];
        __syncthreads();
    }
    float inv = 1.0f / red[0];
    for (int w = tid; w < NNODE; w += 256)
        g_adp[v * NNODE + w] = sm[w] * inv;
}

// -------------------- start 1x1 conv (CIN=2 -> RC) --------------------------
__global__ void start_kernel(const float* __restrict__ x,
                             const float* __restrict__ w,
                             const float* __restrict__ b) {
    int idx = blockIdx.x * blockDim.x + threadIdx.x;
    if (idx >= BATCH * NNODE * L0 * RC) return;
    int c = idx & 31;
    int t = idx >> 5;
    int l = t % L0; t /= L0;
    int n = t % NNODE; t /= NNODE;
    int bb = t;
    const float* xp = x + (((size_t)bb * L0 + l) * NNODE + n) * 2;
    g_h0[idx] = w[c * 2 + 0] * xp[0] + w[c * 2 + 1] * xp[1] + b[c];
}

// -------------------- tcn: one warp per (b,n), all time steps --------------
// lane = channel. Math + global indexing identical to R9's proven kernel.
template<int LIN, int DIL>
__global__ __launch_bounds__(256)
void tcn_fast_kernel(int hin_sel,
                     const float* __restrict__ tcn_w,
                     const float* __restrict__ tcn_b,
                     const float* __restrict__ gcn_w,
                     int layer, int write_y) {
    constexpr int LOUT = LIN - DIL;
    __shared__ float w0s[32][32], w1s[32][32], gws[32][32], sb[32];
    int tid = threadIdx.x;
    for (int i = tid; i < 1024; i += 256) {
        int o = i >> 5, c = i & 31;
        w0s[c][o] = tcn_w[(o * 32 + c) * 2 + 0];
        w1s[c][o] = tcn_w[(o * 32 + c) * 2 + 1];
        gws[c][o] = gcn_w[o * 32 + c];
    }
    if (tid < 32) sb[tid] = tcn_b[tid];
    __syncthreads();

    const float* h_in = hin_sel ? g_h1 : g_h0;
    int lane = tid & 31, warp = tid >> 5;
    int bn = blockIdx.x * 8 + warp;          // grid is exactly 16384/8

    const float* hp = h_in + (size_t)bn * (LIN * 32);
    float h[LIN];
#pragma unroll
    for (int l = 0; l < LIN; l++) h[l] = hp[l * 32 + lane];

    float acc[LOUT];
#pragma unroll
    for (int l = 0; l < LOUT; l++) acc[l] = sb[lane];

#pragma unroll
    for (int c = 0; c < 32; c++) {
        float hl[LIN];
#pragma unroll
        for (int l = 0; l < LIN; l++)
            hl[l] = __shfl_sync(0xffffffffu, h[l], c);
        float w0 = w0s[c][lane], w1 = w1s[c][lane];
#pragma unroll
        for (int l = 0; l < LOUT; l++) {
            acc[l] = fmaf(w0, hl[l], acc[l]);
            acc[l] = fmaf(w1, hl[l + DIL], acc[l]);
        }
    }

    float gate[LOUT];
#pragma unroll
    for (int l = 0; l < LOUT; l++)
        gate[l] = tanhf(acc[l]) * (1.0f / (1.0f + __expf(-acc[l])));

    if (write_y) {
        float y[LOUT];
#pragma unroll
        for (int l = 0; l < LOUT; l++) y[l] = 0.f;
#pragma unroll
        for (int c = 0; c < 32; c++) {
            float gw = gws[c][lane];
#pragma unroll
            for (int l = 0; l < LOUT; l++) {
                float gl = __shfl_sync(0xffffffffu, gate[l], c);
                y[l] = fmaf(gw, gl, y[l]);
            }
        }
        float* yp = g_y + (size_t)bn * (LOUT * 32);
#pragma unroll
        for (int l = 0; l < LOUT; l++) yp[l * 32 + lane] = y[l];
    }
    g_glast[(size_t)bn * 256 + layer * 32 + lane] = gate[LOUT - 1];
}

// -------------------- diffusion GEMM + epilogue (R9-proven) -----------------
#define BM 128
#define BN 64
#define BK 16
__global__ __launch_bounds__(256)
void gcn_gemm_kernel(int hin_sel,
                     const float* __restrict__ gcn_b,
                     const float* __restrict__ bn_g,
                     const float* __restrict__ bn_be,
                     const float* __restrict__ bn_m,
                     const float* __restrict__ bn_v,
                     int L_in, int L_out, int dil) {
    __shared__ float As[BK][BM];
    __shared__ float Bs[BK][BN];
    const float* h_in  = hin_sel ? g_h1 : g_h0;
    float*       h_out = hin_sel ? g_h0 : g_h1;

    int ld = L_out * 32;
    int b  = blockIdx.z;
    int m0 = blockIdx.y * BM;
    int n0 = blockIdx.x * BN;
    int tid = threadIdx.x;
    int tx = tid & 15, ty = tid >> 4;
    const float* Yb = g_y + (size_t)b * NNODE * ld;

    float acc[8][4];
#pragma unroll
    for (int i = 0; i < 8; i++)
#pragma unroll
        for (int j = 0; j < 4; j++) acc[i][j] = 0.f;

    for (int k0 = 0; k0 < NNODE; k0 += BK) {
#pragma unroll
        for (int i = 0; i < 8; i++) {
            int idx = tid + i * 256;
            int k = idx >> 7, m = idx & 127;
            As[k][m] = g_adp[(size_t)(k0 + k) * NNODE + m0 + m];
        }
#pragma unroll
        for (int i = 0; i < 4; i++) {
            int idx = tid + i * 256;
            int k = idx >> 6, n = idx & 63;
            int j = n0 + n;
            Bs[k][n] = (j < ld) ? Yb[(size_t)(k0 + k) * ld + j] : 0.f;
        }
        __syncthreads();
#pragma unroll
        for (int k = 0; k < BK; k++) {
            float a[8], bb[4];
#pragma unroll
            for (int i = 0; i < 8; i++) a[i] = As[k][ty * 8 + i];
#pragma unroll
            for (int j = 0; j < 4; j++) bb[j] = Bs[k][tx * 4 + j];
#pragma unroll
            for (int i = 0; i < 8; i++)
#pragma unroll
                for (int j = 0; j < 4; j++)
                    acc[i][j] = fmaf(a[i], bb[j], acc[i][j]);
        }
        __syncthreads();
    }

#pragma unroll
    for (int j = 0; j < 4; j++) {
        int jj = n0 + tx * 4 + j;
        if (jj >= ld) continue;
        int l = jj >> 5, r = jj & 31;
        float gb  = gcn_b[r];
        float inv = bn_g[r] * rsqrtf(bn_v[r] + BN_EPS);
        float mu  = bn_m[r], be = bn_be[r];
#pragma unroll
        for (int i = 0; i < 8; i++) {
            int w = m0 + ty * 8 + i;
            float val = fmaxf(acc[i][j] + gb, 0.f);
            val += h_in[(((size_t)b * NNODE + w) * L_in + l + dil) * 32 + r];
            val = (val - mu) * inv + be;
            h_out[(((size_t)b * NNODE + w) * L_out + l) * 32 + r] = val;
        }
    }
}

// -------------------- prep: combined skip weights [s][k] + summed bias -----
__global__ void prep_kernel(const float* __restrict__ skip_w,
                            const float* __restrict__ skip_b) {
    int idx = blockIdx.x * blockDim.x + threadIdx.x;
    if (idx < 256 * 256) {
        int s = idx >> 8, k = idx & 255;
        g_W2[idx] = skip_w[(size_t)(k >> 5) * (SC * 32) + s * 32 + (k & 31)];
    } else if (idx < 256 * 256 + 256) {
        int s = idx - 256 * 256;
        float acc = 0.f;
#pragma unroll
        for (int i = 0; i < 8; i++) acc += skip_b[i * 256 + s];
        g_sb2[s] = acc;
    }
}

// -------------------- batched skip GEMM (R9-proven) --------------------------
__global__ __launch_bounds__(256)
void skip_gemm_kernel() {
    __shared__ float As[BK][BM];
    __shared__ float Bs[BK][BN];
    int m0 = blockIdx.y * BM;
    int n0 = blockIdx.x * BN;
    int tid = threadIdx.x;
    int tx = tid & 15, ty = tid >> 4;

    float acc[8][4];
#pragma unroll
    for (int i = 0; i < 8; i++)
#pragma unroll
        for (int j = 0; j < 4; j++) acc[i][j] = 0.f;

    for (int k0 = 0; k0 < 256; k0 += BK) {
        {
            int m = tid & 127, kh = tid >> 7;
            const float* gp = g_glast + (size_t)(m0 + m) * 256 + k0 + kh * 8;
#pragma unroll
            for (int j = 0; j < 8; j++) As[kh * 8 + j][m] = gp[j];
        }
        {
            int n = tid & 63, kq = tid >> 6;
            const float* wp = g_W2 + (size_t)(n0 + n) * 256 + k0 + kq * 4;
#pragma unroll
            for (int j = 0; j < 4; j++) Bs[kq * 4 + j][n] = wp[j];
        }
        __syncthreads();
#pragma unroll
        for (int k = 0; k < BK; k++) {
            float a[8], bb[4];
#pragma unroll
            for (int i = 0; i < 8; i++) a[i] = As[k][ty * 8 + i];
#pragma unroll
            for (int j = 0; j < 4; j++) bb[j] = Bs[k][tx * 4 + j];
#pragma unroll
            for (int i = 0; i < 8; i++)
#pragma unroll
                for (int j = 0; j < 4; j++)
                    acc[i][j] = fmaf(a[i], bb[j], acc[i][j]);
        }
        __syncthreads();
    }
#pragma unroll
    for (int j = 0; j < 4; j++) {
        int s = n0 + tx * 4 + j;
        float be = g_sb2[s];
#pragma unroll
        for (int i = 0; i < 8; i++) {
            int p = m0 + ty * 8 + i;
            g_skip[(size_t)p * SC + s] = acc[i][j] + be;
        }
    }
}

// -------------------- end1: relu(skip) -> 512, relu (R9-proven) --------------
__global__ __launch_bounds__(256)
void end1_kernel(const float* __restrict__ w, const float* __restrict__ bias) {
    __shared__ float As[BK][BM];
    __shared__ float Bs[BK][BN];
    int m0 = blockIdx.y * BM;
    int n0 = blockIdx.x * BN;
    int tid = threadIdx.x;
    int tx = tid & 15, ty = tid >> 4;

    float acc[8][4];
#pragma unroll
    for (int i = 0; i < 8; i++)
#pragma unroll
        for (int j = 0; j < 4; j++) acc[i][j] = 0.f;

    for (int k0 = 0; k0 < SC; k0 += BK) {
        {
            int m = tid & 127, kh = tid >> 7;
            const float* sp = g_skip + (size_t)(m0 + m) * SC + k0 + kh * 8;
#pragma unroll
            for (int j = 0; j < 8; j++) As[kh * 8 + j][m] = fmaxf(sp[j], 0.f);
        }
        {
            int n = tid & 63, kq = tid >> 6;
            const float* wp = w + (size_t)(n0 + n) * SC + k0 + kq * 4;
#pragma unroll
            for (int j = 0; j < 4; j++) Bs[kq * 4 + j][n] = wp[j];
        }
        __syncthreads();
#pragma unroll
        for (int k = 0; k < BK; k++) {
            float a[8], bb[4];
#pragma unroll
            for (int i = 0; i < 8; i++) a[i] = As[k][ty * 8 + i];
#pragma unroll
            for (int j = 0; j < 4; j++) bb[j] = Bs[k][tx * 4 + j];
#pragma unroll
            for (int i = 0; i < 8; i++)
#pragma unroll
                for (int j = 0; j < 4; j++)
                    acc[i][j] = fmaf(a[i], bb[j], acc[i][j]);
        }
        __syncthreads();
    }
#pragma unroll
    for (int j = 0; j < 4; j++) {
        int e = n0 + tx * 4 + j;
        float be = bias[e];
#pragma unroll
        for (int i = 0; i < 8; i++) {
            int p = m0 + ty * 8 + i;
            g_c1[(size_t)p * EC + e] = fmaxf(acc[i][j] + be, 0.f);
        }
    }
}

// -------------------- end2: 512 -> 12, write output (R9-proven) --------------
__global__ __launch_bounds__(128)
void end2_kernel(const float* __restrict__ w, const float* __restrict__ bias,
                 float* __restrict__ out) {
    __shared__ float ws[OCH][EC];
    int tid = threadIdx.x;
    for (int i = tid; i < OCH * EC; i += 128) ws[i / EC][i % EC] = w[i];
    __syncthreads();
    int p = blockIdx.x * 128 + tid;
    if (p >= BATCH * NNODE) return;
    const float* cp = g_c1 + (size_t)p * EC;
    float acc[OCH];
#pragma unroll
    for (int o = 0; o < OCH; o++) acc[o] = bias[o];
    for (int e = 0; e < EC; e += 4) {
        float4 v = *(const float4*)(cp + e);
#pragma unroll
        for (int o = 0; o < OCH; o++) {
            acc[o] = fmaf(ws[o][e + 0], v.x, acc[o]);
            acc[o] = fmaf(ws[o][e + 1], v.y, acc[o]);
            acc[o] = fmaf(ws[o][e + 2], v.z, acc[o]);
            acc[o] = fmaf(ws[o][e + 3], v.w, acc[o]);
        }
    }
#pragma unroll
    for (int o = 0; o < OCH; o++) out[(size_t)p * OCH + o] = acc[o];
}

// ---------------------------------------------------------------------------
extern "C" void kernel_launch(void* const* d_in, const int* in_sizes, int n_in,
                              void* d_out, int out_size) {
    const float* x       = (const float*)d_in[0];
    const float* emb     = (const float*)d_in[1];
    const float* start_w = (const float*)d_in[2];
    const float* start_b = (const float*)d_in[3];
    const float* tcn_w   = (const float*)d_in[4];
    const float* tcn_b   = (const float*)d_in[5];
    const float* skip_w  = (const float*)d_in[6];
    const float* skip_b  = (const float*)d_in[7];
    const float* gcn_w   = (const float*)d_in[8];
    const float* gcn_b   = (const float*)d_in[9];
    const float* bn_g    = (const float*)d_in[10];
    const float* bn_be   = (const float*)d_in[11];
    const float* bn_m    = (const float*)d_in[12];
    const float* bn_v    = (const float*)d_in[13];
    const float* e1w     = (const float*)d_in[14];
    const float* e1b     = (const float*)d_in[15];
    const float* e2w     = (const float*)d_in[16];
    const float* e2b     = (const float*)d_in[17];
    float* out = (float*)d_out;

    adp_kernel<<<NNODE, 256>>>(emb);
    start_kernel<<<(BATCH * NNODE * L0 * RC + 255) / 256, 256>>>(x, start_w, start_b);
    prep_kernel<<<(256 * 256 + 256 + 255) / 256, 256>>>(skip_w, skip_b);

    static const int DIL[NLAYER] = {1, 2, 1, 2, 1, 2, 1, 2};
    const int TCN_GRID = (BATCH * NNODE) / 8;   // 2048
    int L_in = L0;
    int hsel = 0;
    for (int i = 0; i < NLAYER; i++) {
        int d = DIL[i];
        int L_out = L_in - d;
        int last = (i == NLAYER - 1);
        const float* tw = tcn_w + (size_t)i * 32 * 32 * 2;
        const float* tb = tcn_b + (size_t)i * 32;
        const float* gw = gcn_w + (size_t)i * 32 * 32;
        int wy = last ? 0 : 1;
        switch (i) {
        case 0: tcn_fast_kernel<13, 1><<<TCN_GRID, 256>>>(hsel, tw, tb, gw, i, wy); break;
        case 1: tcn_fast_kernel<12, 2><<<TCN_GRID, 256>>>(hsel, tw, tb, gw, i, wy); break;
        case 2: tcn_fast_kernel<10, 1><<<TCN_GRID, 256>>>(hsel, tw, tb, gw, i, wy); break;
        case 3: tcn_fast_kernel< 9, 2><<<TCN_GRID, 256>>>(hsel, tw, tb, gw, i, wy); break;
        case 4: tcn_fast_kernel< 7, 1><<<TCN_GRID, 256>>>(hsel, tw, tb, gw, i, wy); break;
        case 5: tcn_fast_kernel< 6, 2><<<TCN_GRID, 256>>>(hsel, tw, tb, gw, i, wy); break;
        case 6: tcn_fast_kernel< 4, 1><<<TCN_GRID, 256>>>(hsel, tw, tb, gw, i, wy); break;
        case 7: tcn_fast_kernel< 3, 2><<<TCN_GRID, 256>>>(hsel, tw, tb, gw, i, wy); break;
        }
        if (!last) {
            int ld = L_out * 32;
            dim3 gridG((ld + BN - 1) / BN, NNODE / BM, BATCH);
            gcn_gemm_kernel<<<gridG, 256>>>(
                hsel,
                gcn_b + (size_t)i * 32,
                bn_g + (size_t)i * 32, bn_be + (size_t)i * 32,
                bn_m + (size_t)i * 32, bn_v + (size_t)i * 32,
                L_in, L_out, d);
            hsel ^= 1;
        }
        L_in = L_out;
    }

    skip_gemm_kernel<<<dim3(SC / BN, (BATCH * NNODE) / BM), 256>>>();
    end1_kernel<<<dim3(EC / BN, (BATCH * NNODE) / BM), 256>>>(e1w, e1b);
    end2_kernel<<<((BATCH * NNODE) + 127) / 128, 128>>>(e2w, e2b, out);
}

// round 16
// speedup vs baseline: 2.0168x; 1.1705x over previous
#include <cuda_runtime.h>
#include <stdint.h>
#include <math.h>

// ---------------------------------------------------------------------------
// GraphWaveNet forward, fp32. Base: Round-12 passing kernel (2766us).
// Delta: gcn_gemm inner product uses packed fma.rn.f32x2 (FFMA2, 2 FMA/instr).
// Layout: h, y are [B, N, L, C] channel-innermost, row index bn = b*NNODE+n.
// ---------------------------------------------------------------------------

#define NLAYER 8
#define BATCH  16
#define NNODE  1024
#define L0     13
#define RC     32
#define DC     32
#define SC     256
#define EC     512
#define OCH    12
#define EMBD   10
#define BN_EPS 1e-5f

// -------------------- device scratch (allocation-free) ---------------------
__device__ float g_adp  [NNODE * NNODE];
__device__ float g_h0   [BATCH * NNODE * L0 * RC];
__device__ float g_h1   [BATCH * NNODE * L0 * RC];
__device__ float g_y    [BATCH * NNODE * 12 * DC];
__device__ float g_glast[BATCH * NNODE * 256];
__device__ float g_skip [BATCH * NNODE * SC];
__device__ float g_c1   [BATCH * NNODE * EC];
__device__ float g_W2   [256 * 256];
__device__ float g_sb2  [256];

// -------------------- packed f32x2 helpers ----------------------------------
__device__ __forceinline__ void ffma2(unsigned long long& d,
                                      unsigned long long a,
                                      unsigned long long b) {
    asm("fma.rn.f32x2 %0, %1, %2, %0;" : "+l"(d) : "l"(a), "l"(b));
}
__device__ __forceinline__ unsigned long long pack2(float lo, float hi) {
    unsigned long long u;
    asm("mov.b64 %0, {%1, %2};" : "=l"(u) : "f"(lo), "f"(hi));
    return u;
}
__device__ __forceinline__ float lo32(unsigned long long u) {
    return __uint_as_float((unsigned)(u & 0xffffffffu));
}
__device__ __forceinline__ float hi32(unsigned long long u) {
    return __uint_as_float((unsigned)(u >> 32));
}

// -------------------- adaptive adjacency: softmax(relu(E E^T)) -------------
__global__ void adp_kernel(const float* __restrict__ emb) {
    __shared__ float sE[EMBD];
    __shared__ float sm[NNODE];
    __shared__ float red[256];
    int v = blockIdx.x;
    int tid = threadIdx.x;
    if (tid < EMBD) sE[tid] = emb[v * EMBD + tid];
    __syncthreads();
    float lmax = -1e30f;
    for (int w = tid; w < NNODE; w += 256) {
        float dot = 0.f;
#pragma unroll
        for (int e = 0; e < EMBD; e++) dot += sE[e] * emb[w * EMBD + e];
        dot = fmaxf(dot, 0.f);
        sm[w] = dot;
        lmax = fmaxf(lmax, dot);
    }
    red[tid] = lmax; __syncthreads();
    for (int s = 128; s > 0; s >>= 1) {
        if (tid < s) red[tid] = fmaxf(red[tid], red[tid + s]);
        __syncthreads();
    }
    float mx = red[0]; __syncthreads();
    float lsum = 0.f;
    for (int w = tid; w < NNODE; w += 256) {
        float e = __expf(sm[w] - mx);
        sm[w] = e;
        lsum += e;
    }
    red[tid] = lsum; __syncthreads();
    for (int s = 128; s > 0; s >>= 1) {
        if (tid < s) red[tid] += red[tid + s];
        __syncthreads();
    }
    float inv = 1.0f / red[0];
    for (int w = tid; w < NNODE; w += 256)
        g_adp[v * NNODE + w] = sm[w] * inv;
}

// -------------------- start 1x1 conv (CIN=2 -> RC) --------------------------
__global__ void start_kernel(const float* __restrict__ x,
                             const float* __restrict__ w,
                             const float* __restrict__ b) {
    int idx = blockIdx.x * blockDim.x + threadIdx.x;
    if (idx >= BATCH * NNODE * L0 * RC) return;
    int c = idx & 31;
    int t = idx >> 5;
    int l = t % L0; t /= L0;
    int n = t % NNODE; t /= NNODE;
    int bb = t;
    const float* xp = x + (((size_t)bb * L0 + l) * NNODE + n) * 2;
    g_h0[idx] = w[c * 2 + 0] * xp[0] + w[c * 2 + 1] * xp[1] + b[c];
}

// -------------------- tcn: one warp per (b,n) (R12-proven) ------------------
template<int LIN, int DIL>
__global__ __launch_bounds__(256)
void tcn_fast_kernel(int hin_sel,
                     const float* __restrict__ tcn_w,
                     const float* __restrict__ tcn_b,
                     const float* __restrict__ gcn_w,
                     int layer, int write_y) {
    constexpr int LOUT = LIN - DIL;
    __shared__ float w0s[32][32], w1s[32][32], gws[32][32], sb[32];
    int tid = threadIdx.x;
    for (int i = tid; i < 1024; i += 256) {
        int o = i >> 5, c = i & 31;
        w0s[c][o] = tcn_w[(o * 32 + c) * 2 + 0];
        w1s[c][o] = tcn_w[(o * 32 + c) * 2 + 1];
        gws[c][o] = gcn_w[o * 32 + c];
    }
    if (tid < 32) sb[tid] = tcn_b[tid];
    __syncthreads();

    const float* h_in = hin_sel ? g_h1 : g_h0;
    int lane = tid & 31, warp = tid >> 5;
    int bn = blockIdx.x * 8 + warp;

    const float* hp = h_in + (size_t)bn * (LIN * 32);
    float h[LIN];
#pragma unroll
    for (int l = 0; l < LIN; l++) h[l] = hp[l * 32 + lane];

    float acc[LOUT];
#pragma unroll
    for (int l = 0; l < LOUT; l++) acc[l] = sb[lane];

#pragma unroll
    for (int c = 0; c < 32; c++) {
        float hl[LIN];
#pragma unroll
        for (int l = 0; l < LIN; l++)
            hl[l] = __shfl_sync(0xffffffffu, h[l], c);
        float w0 = w0s[c][lane], w1 = w1s[c][lane];
#pragma unroll
        for (int l = 0; l < LOUT; l++) {
            acc[l] = fmaf(w0, hl[l], acc[l]);
            acc[l] = fmaf(w1, hl[l + DIL], acc[l]);
        }
    }

    float gate[LOUT];
#pragma unroll
    for (int l = 0; l < LOUT; l++)
        gate[l] = tanhf(acc[l]) * (1.0f / (1.0f + __expf(-acc[l])));

    if (write_y) {
        float y[LOUT];
#pragma unroll
        for (int l = 0; l < LOUT; l++) y[l] = 0.f;
#pragma unroll
        for (int c = 0; c < 32; c++) {
            float gw = gws[c][lane];
#pragma unroll
            for (int l = 0; l < LOUT; l++) {
                float gl = __shfl_sync(0xffffffffu, gate[l], c);
                y[l] = fmaf(gw, gl, y[l]);
            }
        }
        float* yp = g_y + (size_t)bn * (LOUT * 32);
#pragma unroll
        for (int l = 0; l < LOUT; l++) yp[l * 32 + lane] = y[l];
    }
    g_glast[(size_t)bn * 256 + layer * 32 + lane] = gate[LOUT - 1];
}

// -------------------- diffusion GEMM + epilogue (f32x2 core) -----------------
// C[w,j] = sum_v adp[v,w] * Y_b[v,j]  — smem fills + epilogue R9-verbatim;
// inner product packs adjacent m rows into fma.rn.f32x2.
#define BM 128
#define BN 64
#define BK 16
__global__ __launch_bounds__(256)
void gcn_gemm_kernel(int hin_sel,
                     const float* __restrict__ gcn_b,
                     const float* __restrict__ bn_g,
                     const float* __restrict__ bn_be,
                     const float* __restrict__ bn_m,
                     const float* __restrict__ bn_v,
                     int L_in, int L_out, int dil) {
    __shared__ float As[BK][BM];
    __shared__ float Bs[BK][BN];
    const float* h_in  = hin_sel ? g_h1 : g_h0;
    float*       h_out = hin_sel ? g_h0 : g_h1;

    int ld = L_out * 32;
    int b  = blockIdx.z;
    int m0 = blockIdx.y * BM;
    int n0 = blockIdx.x * BN;
    int tid = threadIdx.x;
    int tx = tid & 15, ty = tid >> 4;
    const float* Yb = g_y + (size_t)b * NNODE * ld;

    // acc[mi][j] packs rows (ty*8 + 2*mi, +1), col tx*4+j
    unsigned long long acc[4][4];
#pragma unroll
    for (int mi = 0; mi < 4; mi++)
#pragma unroll
        for (int j = 0; j < 4; j++) acc[mi][j] = 0ULL;

    for (int k0 = 0; k0 < NNODE; k0 += BK) {
#pragma unroll
        for (int i = 0; i < 8; i++) {
            int idx = tid + i * 256;
            int k = idx >> 7, m = idx & 127;
            As[k][m] = g_adp[(size_t)(k0 + k) * NNODE + m0 + m];
        }
#pragma unroll
        for (int i = 0; i < 4; i++) {
            int idx = tid + i * 256;
            int k = idx >> 6, n = idx & 63;
            int j = n0 + n;
            Bs[k][n] = (j < ld) ? Yb[(size_t)(k0 + k) * ld + j] : 0.f;
        }
        __syncthreads();
#pragma unroll
        for (int k = 0; k < BK; k++) {
            unsigned long long a2[4];
#pragma unroll
            for (int mi = 0; mi < 4; mi++)
                a2[mi] = *(const unsigned long long*)&As[k][ty * 8 + mi * 2];
#pragma unroll
            for (int j = 0; j < 4; j++) {
                float bv = Bs[k][tx * 4 + j];
                unsigned long long bd = pack2(bv, bv);
#pragma unroll
                for (int mi = 0; mi < 4; mi++)
                    ffma2(acc[mi][j], a2[mi], bd);
            }
        }
        __syncthreads();
    }

#pragma unroll
    for (int j = 0; j < 4; j++) {
        int jj = n0 + tx * 4 + j;
        if (jj >= ld) continue;
        int l = jj >> 5, r = jj & 31;
        float gb  = gcn_b[r];
        float inv = bn_g[r] * rsqrtf(bn_v[r] + BN_EPS);
        float mu  = bn_m[r], be = bn_be[r];
#pragma unroll
        for (int mi = 0; mi < 4; mi++) {
#pragma unroll
            for (int p = 0; p < 2; p++) {
                int w = m0 + ty * 8 + mi * 2 + p;
                float cv = p ? hi32(acc[mi][j]) : lo32(acc[mi][j]);
                float val = fmaxf(cv + gb, 0.f);
                val += h_in[(((size_t)b * NNODE + w) * L_in + l + dil) * 32 + r];
                val = (val - mu) * inv + be;
                h_out[(((size_t)b * NNODE + w) * L_out + l) * 32 + r] = val;
            }
        }
    }
}

// -------------------- prep: combined skip weights [s][k] + summed bias -----
__global__ void prep_kernel(const float* __restrict__ skip_w,
                            const float* __restrict__ skip_b) {
    int idx = blockIdx.x * blockDim.x + threadIdx.x;
    if (idx < 256 * 256) {
        int s = idx >> 8, k = idx & 255;
        g_W2[idx] = skip_w[(size_t)(k >> 5) * (SC * 32) + s * 32 + (k & 31)];
    } else if (idx < 256 * 256 + 256) {
        int s = idx - 256 * 256;
        float acc = 0.f;
#pragma unroll
        for (int i = 0; i < 8; i++) acc += skip_b[i * 256 + s];
        g_sb2[s] = acc;
    }
}

// -------------------- batched skip GEMM (R9-proven) --------------------------
__global__ __launch_bounds__(256)
void skip_gemm_kernel() {
    __shared__ float As[BK][BM];
    __shared__ float Bs[BK][BN];
    int m0 = blockIdx.y * BM;
    int n0 = blockIdx.x * BN;
    int tid = threadIdx.x;
    int tx = tid & 15, ty = tid >> 4;

    float acc[8][4];
#pragma unroll
    for (int i = 0; i < 8; i++)
#pragma unroll
        for (int j = 0; j < 4; j++) acc[i][j] = 0.f;

    for (int k0 = 0; k0 < 256; k0 += BK) {
        {
            int m = tid & 127, kh = tid >> 7;
            const float* gp = g_glast + (size_t)(m0 + m) * 256 + k0 + kh * 8;
#pragma unroll
            for (int j = 0; j < 8; j++) As[kh * 8 + j][m] = gp[j];
        }
        {
            int n = tid & 63, kq = tid >> 6;
            const float* wp = g_W2 + (size_t)(n0 + n) * 256 + k0 + kq * 4;
#pragma unroll
            for (int j = 0; j < 4; j++) Bs[kq * 4 + j][n] = wp[j];
        }
        __syncthreads();
#pragma unroll
        for (int k = 0; k < BK; k++) {
            float a[8], bb[4];
#pragma unroll
            for (int i = 0; i < 8; i++) a[i] = As[k][ty * 8 + i];
#pragma unroll
            for (int j = 0; j < 4; j++) bb[j] = Bs[k][tx * 4 + j];
#pragma unroll
            for (int i = 0; i < 8; i++)
#pragma unroll
                for (int j = 0; j < 4; j++)
                    acc[i][j] = fmaf(a[i], bb[j], acc[i][j]);
        }
        __syncthreads();
    }
#pragma unroll
    for (int j = 0; j < 4; j++) {
        int s = n0 + tx * 4 + j;
        float be = g_sb2[s];
#pragma unroll
        for (int i = 0; i < 8; i++) {
            int p = m0 + ty * 8 + i;
            g_skip[(size_t)p * SC + s] = acc[i][j] + be;
        }
    }
}

// -------------------- end1: relu(skip) -> 512, relu (R9-proven) --------------
__global__ __launch_bounds__(256)
void end1_kernel(const float* __restrict__ w, const float* __restrict__ bias) {
    __shared__ float As[BK][BM];
    __shared__ float Bs[BK][BN];
    int m0 = blockIdx.y * BM;
    int n0 = blockIdx.x * BN;
    int tid = threadIdx.x;
    int tx = tid & 15, ty = tid >> 4;

    float acc[8][4];
#pragma unroll
    for (int i = 0; i < 8; i++)
#pragma unroll
        for (int j = 0; j < 4; j++) acc[i][j] = 0.f;

    for (int k0 = 0; k0 < SC; k0 += BK) {
        {
            int m = tid & 127, kh = tid >> 7;
            const float* sp = g_skip + (size_t)(m0 + m) * SC + k0 + kh * 8;
#pragma unroll
            for (int j = 0; j < 8; j++) As[kh * 8 + j][m] = fmaxf(sp[j], 0.f);
        }
        {
            int n = tid & 63, kq = tid >> 6;
            const float* wp = w + (size_t)(n0 + n) * SC + k0 + kq * 4;
#pragma unroll
            for (int j = 0; j < 4; j++) Bs[kq * 4 + j][n] = wp[j];
        }
        __syncthreads();
#pragma unroll
        for (int k = 0; k < BK; k++) {
            float a[8], bb[4];
#pragma unroll
            for (int i = 0; i < 8; i++) a[i] = As[k][ty * 8 + i];
#pragma unroll
            for (int j = 0; j < 4; j++) bb[j] = Bs[k][tx * 4 + j];
#pragma unroll
            for (int i = 0; i < 8; i++)
#pragma unroll
                for (int j = 0; j < 4; j++)
                    acc[i][j] = fmaf(a[i], bb[j], acc[i][j]);
        }
        __syncthreads();
    }
#pragma unroll
    for (int j = 0; j < 4; j++) {
        int e = n0 + tx * 4 + j;
        float be = bias[e];
#pragma unroll
        for (int i = 0; i < 8; i++) {
            int p = m0 + ty * 8 + i;
            g_c1[(size_t)p * EC + e] = fmaxf(acc[i][j] + be, 0.f);
        }
    }
}

// -------------------- end2: 512 -> 12, write output (R9-proven) --------------
__global__ __launch_bounds__(128)
void end2_kernel(const float* __restrict__ w, const float* __restrict__ bias,
                 float* __restrict__ out) {
    __shared__ float ws[OCH][EC];
    int tid = threadIdx.x;
    for (int i = tid; i < OCH * EC; i += 128) ws[i / EC][i % EC] = w[i];
    __syncthreads();
    int p = blockIdx.x * 128 + tid;
    if (p >= BATCH * NNODE) return;
    const float* cp = g_c1 + (size_t)p * EC;
    float acc[OCH];
#pragma unroll
    for (int o = 0; o < OCH; o++) acc[o] = bias[o];
    for (int e = 0; e < EC; e += 4) {
        float4 v = *(const float4*)(cp + e);
#pragma unroll
        for (int o = 0; o < OCH; o++) {
            acc[o] = fmaf(ws[o][e + 0], v.x, acc[o]);
            acc[o] = fmaf(ws[o][e + 1], v.y, acc[o]);
            acc[o] = fmaf(ws[o][e + 2], v.z, acc[o]);
            acc[o] = fmaf(ws[o][e + 3], v.w, acc[o]);
        }
    }
#pragma unroll
    for (int o = 0; o < OCH; o++) out[(size_t)p * OCH + o] = acc[o];
}

// ---------------------------------------------------------------------------
extern "C" void kernel_launch(void* const* d_in, const int* in_sizes, int n_in,
                              void* d_out, int out_size) {
    const float* x       = (const float*)d_in[0];
    const float* emb     = (const float*)d_in[1];
    const float* start_w = (const float*)d_in[2];
    const float* start_b = (const float*)d_in[3];
    const float* tcn_w   = (const float*)d_in[4];
    const float* tcn_b   = (const float*)d_in[5];
    const float* skip_w  = (const float*)d_in[6];
    const float* skip_b  = (const float*)d_in[7];
    const float* gcn_w   = (const float*)d_in[8];
    const float* gcn_b   = (const float*)d_in[9];
    const float* bn_g    = (const float*)d_in[10];
    const float* bn_be   = (const float*)d_in[11];
    const float* bn_m    = (const float*)d_in[12];
    const float* bn_v    = (const float*)d_in[13];
    const float* e1w     = (const float*)d_in[14];
    const float* e1b     = (const float*)d_in[15];
    const float* e2w     = (const float*)d_in[16];
    const float* e2b     = (const float*)d_in[17];
    float* out = (float*)d_out;

    adp_kernel<<<NNODE, 256>>>(emb);
    start_kernel<<<(BATCH * NNODE * L0 * RC + 255) / 256, 256>>>(x, start_w, start_b);
    prep_kernel<<<(256 * 256 + 256 + 255) / 256, 256>>>(skip_w, skip_b);

    static const int DIL[NLAYER] = {1, 2, 1, 2, 1, 2, 1, 2};
    const int TCN_GRID = (BATCH * NNODE) / 8;   // 2048
    int L_in = L0;
    int hsel = 0;
    for (int i = 0; i < NLAYER; i++) {
        int d = DIL[i];
        int L_out = L_in - d;
        int last = (i == NLAYER - 1);
        const float* tw = tcn_w + (size_t)i * 32 * 32 * 2;
        const float* tb = tcn_b + (size_t)i * 32;
        const float* gw = gcn_w + (size_t)i * 32 * 32;
        int wy = last ? 0 : 1;
        switch (i) {
        case 0: tcn_fast_kernel<13, 1><<<TCN_GRID, 256>>>(hsel, tw, tb, gw, i, wy); break;
        case 1: tcn_fast_kernel<12, 2><<<TCN_GRID, 256>>>(hsel, tw, tb, gw, i, wy); break;
        case 2: tcn_fast_kernel<10, 1><<<TCN_GRID, 256>>>(hsel, tw, tb, gw, i, wy); break;
        case 3: tcn_fast_kernel< 9, 2><<<TCN_GRID, 256>>>(hsel, tw, tb, gw, i, wy); break;
        case 4: tcn_fast_kernel< 7, 1><<<TCN_GRID, 256>>>(hsel, tw, tb, gw, i, wy); break;
        case 5: tcn_fast_kernel< 6, 2><<<TCN_GRID, 256>>>(hsel, tw, tb, gw, i, wy); break;
        case 6: tcn_fast_kernel< 4, 1><<<TCN_GRID, 256>>>(hsel, tw, tb, gw, i, wy); break;
        case 7: tcn_fast_kernel< 3, 2><<<TCN_GRID, 256>>>(hsel, tw, tb, gw, i, wy); break;
        }
        if (!last) {
            int ld = L_out * 32;
            dim3 gridG((ld + BN - 1) / BN, NNODE / BM, BATCH);
            gcn_gemm_kernel<<<gridG, 256>>>(
                hsel,
                gcn_b + (size_t)i * 32,
                bn_g + (size_t)i * 32, bn_be + (size_t)i * 32,
                bn_m + (size_t)i * 32, bn_v + (size_t)i * 32,
                L_in, L_out, d);
            hsel ^= 1;
        }
        L_in = L_out;
    }

    skip_gemm_kernel<<<dim3(SC / BN, (BATCH * NNODE) / BM), 256>>>();
    end1_kernel<<<dim3(EC / BN, (BATCH * NNODE) / BM), 256>>>(e1w, e1b);
    end2_kernel<<<((BATCH * NNODE) + 127) / 128, 128>>>(e2w, e2b, out);
}